// round 6
// baseline (speedup 1.0000x reference)
#include <cuda_runtime.h>
#include <stdint.h>

// weights[T=8] f32; bond_src/dst/type [B=1024,E=512] i32 (+1 node offset);
// out [B,256,256] f32 (256 MiB) -> HBM-write-bound.
//
// One block per batch:
//   phase 0: smem hash dedup (reference last-write-wins ordering via priorities)
//   phase 1: pure streaming zero-fill of the 256 KB slice (unrolled STG.128,
//            ~1 inst/store; overlaps with the smem atomic inserts)
//   phase 2: winners overwrite their cells with 4B stores (byte-masked sector
//            writes -> no read-for-ownership even on L2 miss)
static constexpr int Bb      = 1024;
static constexpr int E       = 512;
static constexpr int Nn      = 256;
static constexpr int CELLS   = Nn * Nn;     // 65536 cells / batch
static constexpr int TS      = 2048;        // hash slots (<=0.5 load)
static constexpr int THREADS = 512;

__device__ __forceinline__ uint32_t ht_hash(uint32_t key) {
    return (key * 2654435761u) >> (32 - 11);          // -> [0, 2048)
}

// Entry: key(16b hi) | prio(16b lo). key in [257,65535] so entry!=0 when valid.
__device__ __forceinline__ void ht_insert(uint32_t* table, uint32_t key, uint32_t prio) {
    uint32_t entry = (key << 16) | prio;
    uint32_t h = ht_hash(key);
    #pragma unroll 1
    while (true) {
        uint32_t cur = table[h];
        if (cur == 0u) {
            uint32_t old = atomicCAS(&table[h], 0u, entry);
            if (old == 0u) return;
            cur = old;
        }
        if ((cur >> 16) == key) {          // same cell: max prio wins (hi bits equal)
            atomicMax(&table[h], entry);
            return;
        }
        h = (h + 1) & (TS - 1);
    }
}

__device__ __forceinline__ uint32_t ht_find_slot(const uint32_t* table, uint32_t key) {
    uint32_t h = ht_hash(key);
    #pragma unroll 1
    while ((table[h] >> 16) != key) h = (h + 1) & (TS - 1);
    return h;
}

__global__ __launch_bounds__(THREADS, 4)
void bond_weight_kernel(const float* __restrict__ weights,
                        const int*   __restrict__ bond_src,
                        const int*   __restrict__ bond_dst,
                        const int*   __restrict__ bond_type,
                        float*       __restrict__ out)
{
    __shared__ uint32_t table[TS];          // key|prio (8 KB) — only smem we need now

    const int b = blockIdx.x;
    const int t = threadIdx.x;

    // ---- clear hash table ----
    #pragma unroll
    for (int i = 0; i < TS / THREADS; i++)
        table[t + i * THREADS] = 0u;

    // ---- this thread's edge ----
    const int   eidx = b * E + t;                  // 512 threads == 512 edges
    const int   s = bond_src[eidx] + 1;            // 1..255
    const int   d = bond_dst[eidx] + 1;
    const float w = weights[bond_type[eidx]];

    const uint32_t key1  = (uint32_t)(s * Nn + d); // pass 0: [src,dst]
    const uint32_t key2  = (uint32_t)(d * Nn + s); // pass 1: [dst,src]
    const uint32_t prio1 = (uint32_t)(t + 1);      // ref: pass0 e=0..E-1, then pass1;
    const uint32_t prio2 = (uint32_t)(E + t + 1);  // later application wins

    __syncthreads();   // table clear visible before inserts

    // ---- dedup inserts (smem atomics) ----
    ht_insert(table, key1, prio1);
    ht_insert(table, key2, prio2);

    // ---- pure streaming zero-fill: 32 x STG.128 per thread, unrolled,
    //      base + immediate offsets => ~1 issue per 16B; hides insert latency ----
    {
        float4* o4 = reinterpret_cast<float4*>(out + (size_t)b * CELLS) + t;
        const float4 z = make_float4(0.f, 0.f, 0.f, 0.f);
        #pragma unroll
        for (int i = 0; i < (CELLS / 4) / THREADS; i++)     // 32 stores
            __stcs(o4 + i * THREADS, z);                    // coalesced, evict-first
    }

    __syncthreads();   // inserts final AND all zero stores ordered before phase 2

    // ---- winners overwrite their cells (4B byte-masked stores; no RFO) ----
    float* o = out + (size_t)b * CELLS;
    {
        uint32_t s1 = ht_find_slot(table, key1);
        if ((table[s1] & 0xFFFFu) == prio1) o[key1] = w;
        uint32_t s2 = ht_find_slot(table, key2);
        if ((table[s2] & 0xFFFFu) == prio2) o[key2] = w;
    }
}

extern "C" void kernel_launch(void* const* d_in, const int* in_sizes, int n_in,
                              void* d_out, int out_size)
{
    const float* weights   = (const float*)d_in[0];
    const int*   bond_src  = (const int*)  d_in[1];
    const int*   bond_dst  = (const int*)  d_in[2];
    const int*   bond_type = (const int*)  d_in[3];
    float* out = (float*)d_out;

    bond_weight_kernel<<<Bb, THREADS>>>(weights, bond_src, bond_dst, bond_type, out);
}

// round 7
// speedup vs baseline: 1.4732x; 1.4732x over previous
#include <cuda_runtime.h>
#include <stdint.h>

// weights[T=8] f32; bond_src/dst/type [B=1024,E=512] i32 (+1 node offset);
// out [B,256,256] f32 (256 MiB) -> HBM-write-bound.
// Fused single-pass (R4 structure, proven fastest): per-batch smem hash dedup
// (reference last-write-wins order), bitmap + rank/popcount + compact values,
// then ONE streaming pass writing every 128B line exactly once.
// R7 deltas: 3-CTA launch bounds (reg headroom for MLP), 8-deep explicit
// bitmap-word prefetch, insert returns slot (no re-probe).
static constexpr int Bb      = 1024;
static constexpr int E       = 512;
static constexpr int Nn      = 256;
static constexpr int CELLS   = Nn * Nn;     // 65536 cells / batch
static constexpr int NWORDS  = CELLS / 32;  // 2048 bitmap words
static constexpr int TS      = 2048;        // hash slots (<=0.5 load)
static constexpr int THREADS = 512;
static constexpr int ITERS   = (CELLS / 4) / THREADS;   // 32 float4 per thread
static constexpr int GROUP   = 8;                       // prefetch depth

__device__ __forceinline__ uint32_t ht_hash(uint32_t key) {
    return (key * 2654435761u) >> (32 - 11);            // -> [0, 2048)
}

// Entry: key(16b hi) | prio(16b lo). key in [257,65535] so entry!=0 when valid.
// Returns the slot where `key` resides.
__device__ __forceinline__ uint32_t ht_insert(uint32_t* table, uint32_t key, uint32_t prio) {
    uint32_t entry = (key << 16) | prio;
    uint32_t h = ht_hash(key);
    #pragma unroll 1
    while (true) {
        uint32_t cur = table[h];
        if (cur == 0u) {
            uint32_t old = atomicCAS(&table[h], 0u, entry);
            if (old == 0u) return h;
            cur = old;
        }
        if ((cur >> 16) == key) {          // same cell: max prio wins (hi bits equal)
            atomicMax(&table[h], entry);
            return h;
        }
        h = (h + 1) & (TS - 1);
    }
}

__global__ __launch_bounds__(THREADS, 3)
void bond_weight_kernel(const float* __restrict__ weights,
                        const int*   __restrict__ bond_src,
                        const int*   __restrict__ bond_dst,
                        const int*   __restrict__ bond_type,
                        float*       __restrict__ out)
{
    __shared__ uint32_t table[TS];          // key|prio (8 KB)
    __shared__ uint32_t bitmap[NWORDS];     // occupied cells (8 KB)
    __shared__ uint16_t rankw[NWORDS];      // exclusive prefix popcount per word (4 KB)
    __shared__ float    cvals[2 * E];       // compact winner values, cell-id order (4 KB)
    __shared__ uint32_t warpsum[16];

    const int b = blockIdx.x;
    const int t = threadIdx.x;

    // ---- clear hash + bitmap ----
    #pragma unroll
    for (int i = 0; i < NWORDS / THREADS; i++) {
        table [t + i * THREADS] = 0u;
        bitmap[t + i * THREADS] = 0u;
    }

    // ---- this thread's edge ----
    const int   eidx = b * E + t;                  // 512 threads == 512 edges
    const int   s = bond_src[eidx] + 1;            // 1..255
    const int   d = bond_dst[eidx] + 1;
    const float w = weights[bond_type[eidx]];

    const uint32_t key1  = (uint32_t)(s * Nn + d); // pass 0: [src,dst]
    const uint32_t key2  = (uint32_t)(d * Nn + s); // pass 1: [dst,src]
    const uint32_t prio1 = (uint32_t)(t + 1);      // ref: pass0 e=0..E-1, then pass1;
    const uint32_t prio2 = (uint32_t)(E + t + 1);  // later application wins

    __syncthreads();   // clears visible

    const uint32_t slot1 = ht_insert(table, key1, prio1);
    const uint32_t slot2 = ht_insert(table, key2, prio2);
    atomicOr(&bitmap[key1 >> 5], 1u << (key1 & 31));
    atomicOr(&bitmap[key2 >> 5], 1u << (key2 & 31));

    __syncthreads();   // inserts + bitmap final

    // ---- block-wide exclusive prefix sum of per-word popcounts ----
    {
        const int base4 = t * 4;                   // 512 threads x 4 words = 2048
        const uint32_t c0 = __popc(bitmap[base4 + 0]);
        const uint32_t c1 = __popc(bitmap[base4 + 1]);
        const uint32_t c2 = __popc(bitmap[base4 + 2]);
        const uint32_t c3 = __popc(bitmap[base4 + 3]);
        const uint32_t ssum = c0 + c1 + c2 + c3;

        const uint32_t lane = t & 31, wrp = t >> 5;
        uint32_t x = ssum;
        #pragma unroll
        for (int off = 1; off < 32; off <<= 1) {
            uint32_t y = __shfl_up_sync(0xFFFFFFFFu, x, off);
            if (lane >= off) x += y;
        }
        if (lane == 31) warpsum[wrp] = x;          // warp totals (inclusive)
        __syncthreads();
        if (t == 0) {                              // serial scan of 16 warp totals
            uint32_t acc = 0;
            #pragma unroll
            for (int i = 0; i < 16; i++) { uint32_t v = warpsum[i]; warpsum[i] = acc; acc += v; }
        }
        __syncthreads();
        const uint32_t excl = warpsum[wrp] + (x - ssum);   // thread-exclusive prefix
        rankw[base4 + 0] = (uint16_t)(excl);
        rankw[base4 + 1] = (uint16_t)(excl + c0);
        rankw[base4 + 2] = (uint16_t)(excl + c0 + c1);
        rankw[base4 + 3] = (uint16_t)(excl + c0 + c1 + c2);
    }
    __syncthreads();   // rank ready

    // ---- winners deposit values at their compact (cell-id-ordered) position ----
    {
        if ((table[slot1] & 0xFFFFu) == prio1) {
            uint32_t wd = key1 >> 5, bt = key1 & 31;
            uint32_t pos = (uint32_t)rankw[wd] + __popc(bitmap[wd] & ((1u << bt) - 1u));
            cvals[pos] = w;
        }
        if ((table[slot2] & 0xFFFFu) == prio2) {
            uint32_t wd = key2 >> 5, bt = key2 & 31;
            uint32_t pos = (uint32_t)rankw[wd] + __popc(bitmap[wd] & ((1u << bt) - 1u));
            cvals[pos] = w;
        }
    }
    __syncthreads();   // cvals ready

    // ---- single streaming pass; 8-deep bitmap-word prefetch for MLP ----
    float4* o4 = reinterpret_cast<float4*>(out + (size_t)b * CELLS);
    const float4 z = make_float4(0.f, 0.f, 0.f, 0.f);
    const int      wsub = t >> 3;            // word sub-index (8 float4 per word)
    const uint32_t sh   = (t & 7u) * 4u;     // loop-invariant nibble shift
    const uint32_t below = (1u << sh) - 1u;

    #pragma unroll
    for (int g = 0; g < ITERS / GROUP; g++) {
        uint32_t wbuf[GROUP];
        #pragma unroll
        for (int j = 0; j < GROUP; j++)                      // 8 LDS in flight
            wbuf[j] = bitmap[(g * GROUP + j) * 64 + wsub];
        #pragma unroll
        for (int j = 0; j < GROUP; j++) {
            const int i   = g * GROUP + j;
            const int idx = i * THREADS + t;                 // coalesced float4 index
            const uint32_t word = wbuf[j];
            const uint32_t nib  = (word >> sh) & 0xFu;
            float4 v = z;
            if (nib) {                                       // O(1) rare-path
                uint32_t p = (uint32_t)rankw[i * 64 + wsub] + __popc(word & below);
                if (nib & 1u) v.x = cvals[p++];
                if (nib & 2u) v.y = cvals[p++];
                if (nib & 4u) v.z = cvals[p++];
                if (nib & 8u) v.w = cvals[p];
            }
            __stcs(o4 + idx, v);     // streaming: each line written exactly once
        }
    }
}

extern "C" void kernel_launch(void* const* d_in, const int* in_sizes, int n_in,
                              void* d_out, int out_size)
{
    const float* weights   = (const float*)d_in[0];
    const int*   bond_src  = (const int*)  d_in[1];
    const int*   bond_dst  = (const int*)  d_in[2];
    const int*   bond_type = (const int*)  d_in[3];
    float* out = (float*)d_out;

    bond_weight_kernel<<<Bb, THREADS>>>(weights, bond_src, bond_dst, bond_type, out);
}